// round 12
// baseline (speedup 1.0000x reference)
#include <cuda_runtime.h>
#include <cuda_fp16.h>
#include <math_constants.h>

#define BDIM 16
#define CDIM 64
#define HW   441
#define NCLS 10
#define MDIM 2205
#define NQT  7        // q-tiles of 64 (448 padded)
#define NMT  18
#define NSTEP 144
#define NSPL 2
#define SPLS 72
#define EPSN 1e-12f

#define NA4 (BDIM * NQT * 4 * 4 * 32)       // 57344
#define NB4 (NCLS * 2 * NMT * 8 * 2 * 32)   // 184320

__device__ float g_qn[BDIM * HW * CDIM];
__device__ float g_rn[NCLS * MDIM];
__device__ uint4 g_af[NA4];
__device__ uint4 g_bf[NB4];
__device__ float4 g_rowtri[BDIM * NCLS * NQT * 64 * NSPL];

__device__ __forceinline__ unsigned int h2(float lo, float hi) {
    __half2 h = __floats2half2_rn(lo, hi);
    return *reinterpret_cast<unsigned int*>(&h);
}
__device__ __forceinline__ unsigned int maxh2(unsigned int a, unsigned int b) {
    unsigned int d; asm("max.f16x2 %0, %1, %2;" : "=r"(d) : "r"(a), "r"(b)); return d;
}
__device__ __forceinline__ unsigned int minh2(unsigned int a, unsigned int b) {
    unsigned int d; asm("min.f16x2 %0, %1, %2;" : "=r"(d) : "r"(a), "r"(b)); return d;
}
__device__ __forceinline__ void ins3p(unsigned int v, unsigned int &a0, unsigned int &a1, unsigned int &a2) {
    unsigned int n0 = minh2(a0, v); a0 = maxh2(a0, v);
    unsigned int n1 = minh2(a1, n0); a1 = maxh2(a1, n0);
    a2 = maxh2(a2, n1);
}
__device__ __forceinline__ void ins3f(float v, float &a0, float &a1, float &a2) {
    float n0 = fminf(a0, v); a0 = fmaxf(a0, v);
    float n1 = fminf(a1, n0); a1 = fmaxf(a1, n0);
    a2 = fmaxf(a2, n1);
}
// race-free packed merge: snapshot BEFORE mutating
__device__ __forceinline__ void merge3p_shfl(int sh, unsigned int &a0, unsigned int &a1, unsigned int &a2) {
    unsigned int o0 = __shfl_xor_sync(0xffffffffu, a0, sh);
    unsigned int o1 = __shfl_xor_sync(0xffffffffu, a1, sh);
    unsigned int o2 = __shfl_xor_sync(0xffffffffu, a2, sh);
    ins3p(o0, a0, a1, a2); ins3p(o1, a0, a1, a2); ins3p(o2, a0, a1, a2);
}
__device__ __forceinline__ void unp_ins(unsigned int p, float &a0, float &a1, float &a2) {
    float2 f = __half22float2(*reinterpret_cast<__half2*>(&p));
    ins3f(f.x, a0, a1, a2); ins3f(f.y, a0, a1, a2);
}
__device__ __forceinline__ void mma_f16(float c[4], uint4 a, unsigned int b0, unsigned int b1) {
    asm volatile("mma.sync.aligned.m16n8k16.row.col.f32.f16.f16.f32 "
                 "{%0,%1,%2,%3},{%4,%5,%6,%7},{%8,%9},{%0,%1,%2,%3};"
                 : "+f"(c[0]), "+f"(c[1]), "+f"(c[2]), "+f"(c[3])
                 : "r"(a.x), "r"(a.y), "r"(a.z), "r"(a.w), "r"(b0), "r"(b1));
}

// fused fp32 normalize (q and s in one launch)
__global__ void norm_kernel(const float* __restrict__ x1, const float* __restrict__ x2) {
    int idx = blockIdx.x * 256 + threadIdx.x;
    if (idx < BDIM * HW) {
        int b = idx / HW, p = idx - b * HW;
        const float* src = x1 + (b * CDIM) * HW + p;
        float v[CDIM]; float ss = 0.f;
#pragma unroll
        for (int c = 0; c < CDIM; c++) { float x = src[c * HW]; v[c] = x; ss += x * x; }
        float inv = 1.f / fmaxf(sqrtf(ss), EPSN);
        float* dst = g_qn + idx * CDIM;
#pragma unroll
        for (int c = 0; c < CDIM; c++) dst[c] = v[c] * inv;
    } else if (idx < BDIM * HW + NCLS * MDIM) {
        int j = idx - BDIM * HW;
        int n = j / MDIM, m = j - n * MDIM;
        const float* src = x2 + (n * CDIM) * MDIM + m;
        float ss = 0.f;
#pragma unroll
        for (int c = 0; c < CDIM; c++) { float x = src[c * MDIM]; ss += x * x; }
        g_rn[j] = 1.f / fmaxf(sqrtf(ss), EPSN);
    }
}

__global__ void frag_kernel(const float* __restrict__ x2) {
    int idx = blockIdx.x * 256 + threadIdx.x;
    if (idx < NA4) {
        // A: [b][qt][rb][kc][lane]
        int lane = idx & 31; int r = idx >> 5;
        int kc = r & 3;  r >>= 2;
        int rb = r & 3;  r >>= 2;
        int qt = r % 7;  int b = r / 7;
        int q = qt * 64 + rb * 16 + (lane >> 2);
        int k = kc * 16 + 2 * (lane & 3);
        float v0=0.f,v1=0.f,v2=0.f,v3=0.f,v4=0.f,v5=0.f,v6=0.f,v7=0.f;
        if (q < HW) {
            const float* p = g_qn + (b * HW + q) * CDIM;
            v0 = p[k]; v1 = p[k+1]; v2 = p[k+8]; v3 = p[k+9];
        }
        if (q + 8 < HW) {
            const float* p = g_qn + (b * HW + q + 8) * CDIM;
            v4 = p[k]; v5 = p[k+1]; v6 = p[k+8]; v7 = p[k+9];
        }
        uint4 o; o.x = h2(v0, v1); o.y = h2(v4, v5); o.z = h2(v2, v3); o.w = h2(v6, v7);
        g_af[idx] = o;
    } else if (idx < NA4 + NB4) {
        int j = idx - NA4;
        int lane = j & 31; int r = j >> 5;
        int kcp = r & 1; r >>= 1;
        int g = r & 7;   r >>= 3;
        int mt = r % 18; r /= 18;
        int half = r & 1; int n = r >> 1;
        int m = mt * 128 + half * 64 + g * 8 + (lane >> 2);
        int k0 = kcp * 32 + 2 * (lane & 3);
        uint4 o;
        if (m < MDIM) {
            float inv = g_rn[n * MDIM + m];
            const float* base = x2 + (n * CDIM) * MDIM + m;
            o.x = h2(base[(k0)      * MDIM] * inv, base[(k0 + 1)  * MDIM] * inv);
            o.y = h2(base[(k0 + 8)  * MDIM] * inv, base[(k0 + 9)  * MDIM] * inv);
            o.z = h2(base[(k0 + 16) * MDIM] * inv, base[(k0 + 17) * MDIM] * inv);
            o.w = h2(base[(k0 + 24) * MDIM] * inv, base[(k0 + 25) * MDIM] * inv);
        } else { o.x = o.y = o.z = o.w = 0u; }
        g_bf[j] = o;
    }
}

__global__ void __launch_bounds__(256, 4)
fused_metric_kernel() {
    __shared__ unsigned int sRed[4 * 4 * 6];   // 4 rb-warps x 4 quads x 2 triples x 3

    const int t = threadIdx.x;
    const int w = t >> 5, lane = t & 31, l3 = lane & 3;
    const int rb = w & 3, half = w >> 2;
    const int qt = blockIdx.x >> 1, ms = blockIdx.x & 1;
    const int n = blockIdx.y, b = blockIdx.z;
    const int s0 = ms * SPLS, s1 = s0 + SPLS;

    // A: 16 rows, 4 k-chunks resident (16 regs)
    uint4 aR[4];
    {
        const uint4* pa = g_af + (((b * 7 + qt) * 4 + rb) * 4) * 32 + lane;
#pragma unroll
        for (int kc = 0; kc < 4; kc++) aR[kc] = pa[kc * 32];
    }

    const uint4* baseB = g_bf + (n * 2 + half) * 9216 + lane;

    // packed fp16 triples: A = row r, B = row r+8
    unsigned int Aa = 0xFC00FC00u, Ab = 0xFC00FC00u, Ac = 0xFC00FC00u;
    unsigned int Ba = 0xFC00FC00u, Bb = 0xFC00FC00u, Bc = 0xFC00FC00u;

    uint4 c0 = baseB[s0 * 64], c1 = baseB[s0 * 64 + 32];
    const int sMask = (s1 < NSTEP - 8) ? s1 : NSTEP - 8;

#pragma unroll 1
    for (int s = s0; s < s1; s++) {
        int ns = s + 1 < s1 ? s + 1 : s;
        const uint4* pn = baseB + ns * 64;
        uint4 n0 = pn[0], n1 = pn[32];

        float acc[4] = {0.f, 0.f, 0.f, 0.f};
        mma_f16(acc, aR[0], c0.x, c0.y);
        mma_f16(acc, aR[1], c0.z, c0.w);
        mma_f16(acc, aR[2], c1.x, c1.y);
        mma_f16(acc, aR[3], c1.z, c1.w);
        c0 = n0; c1 = n1;

        if (s < sMask) {
            ins3p(h2(acc[0], acc[1]), Aa, Ab, Ac);
            ins3p(h2(acc[2], acc[3]), Ba, Bb, Bc);
        } else if (half == 0) {      // last m-tile: valid cols 0..28
            const float NI = -CUDART_INF_F;
            int col = (s & 7) * 8 + 2 * l3;
            float e0 = (col < 29) ? acc[0] : NI, e1 = (col + 1 < 29) ? acc[1] : NI;
            float e2 = (col < 29) ? acc[2] : NI, e3 = (col + 1 < 29) ? acc[3] : NI;
            ins3p(h2(e0, e1), Aa, Ab, Ac);
            ins3p(h2(e2, e3), Ba, Bb, Bc);
        }
    }

#pragma unroll
    for (int sh = 1; sh <= 2; sh <<= 1) {
        merge3p_shfl(sh, Aa, Ab, Ac);
        merge3p_shfl(sh, Ba, Bb, Bc);
    }

    // cross-half merge via smem
    if (w >= 4 && l3 == 0) {
        unsigned int* d = sRed + (rb * 4 + (lane >> 3)) * 6 + ((lane >> 2) & 1) * 96;
        // note: 8 quads per warp (lane>>2 = 0..7); use flat layout instead:
    }
    __syncthreads();   // placeholder sync removed below — real logic follows
    // --- real publish/combine (8 quads per warp) ---
    __shared__ unsigned int sRed2[4 * 8 * 6];
    if (w >= 4 && l3 == 0) {
        unsigned int* d = sRed2 + (rb * 8 + (lane >> 2)) * 6;
        d[0] = Aa; d[1] = Ab; d[2] = Ac; d[3] = Ba; d[4] = Bb; d[5] = Bc;
    }
    __syncthreads();
    if (w < 4 && l3 == 0) {
        const unsigned int* d = sRed2 + (rb * 8 + (lane >> 2)) * 6;
        ins3p(d[0], Aa, Ab, Ac); ins3p(d[1], Aa, Ab, Ac); ins3p(d[2], Aa, Ab, Ac);
        ins3p(d[3], Ba, Bb, Bc); ins3p(d[4], Ba, Bb, Bc); ins3p(d[5], Ba, Bb, Bc);

        const int entry = (b * NCLS + n) * NQT + qt;
        const int row0 = rb * 16 + (lane >> 2);
        float4* outp = g_rowtri + ((long)entry * 64) * NSPL + ms;
        {
            float u0 = -CUDART_INF_F, u1 = u0, u2 = u0;
            unp_ins(Aa, u0, u1, u2); unp_ins(Ab, u0, u1, u2); unp_ins(Ac, u0, u1, u2);
            outp[row0 * NSPL] = make_float4(u0, u1, u2, 0.f);
        }
        {
            float u0 = -CUDART_INF_F, u1 = u0, u2 = u0;
            unp_ins(Ba, u0, u1, u2); unp_ins(Bb, u0, u1, u2); unp_ins(Bc, u0, u1, u2);
            outp[(row0 + 8) * NSPL] = make_float4(u0, u1, u2, 0.f);
        }
    }
}

// merge split triples per row, sum top-3, reduce over rows
__global__ void finalize_kernel(float* __restrict__ out) {
    __shared__ float red[16];
    const int e = blockIdx.x;          // b*NCLS + n
    const int q = threadIdx.x;         // 0..511
    float val = 0.f;
    if (q < HW) {
        int qt = q >> 6, row = q & 63;
        const float4* p = g_rowtri + ((long)((e * NQT + qt) * 64 + row)) * NSPL;
        float4 u = p[0], v = p[1];
        float t0 = u.x, t1 = u.y, t2 = u.z;
        ins3f(v.x, t0, t1, t2); ins3f(v.y, t0, t1, t2); ins3f(v.z, t0, t1, t2);
        val = t0 + t1 + t2;
    }
    const int w = q >> 5, lane = q & 31;
#pragma unroll
    for (int sh = 16; sh > 0; sh >>= 1) val += __shfl_xor_sync(0xffffffffu, val, sh);
    if (lane == 0) red[w] = val;
    __syncthreads();
    if (w == 0) {
        float x = (lane < 16) ? red[lane] : 0.f;
#pragma unroll
        for (int sh = 8; sh > 0; sh >>= 1) x += __shfl_xor_sync(0xffffffffu, x, sh);
        if (lane == 0) out[e] = x;
    }
}

extern "C" void kernel_launch(void* const* d_in, const int* in_sizes, int n_in,
                              void* d_out, int out_size) {
    const float* x1 = (const float*)d_in[0];
    const float* x2 = (const float*)d_in[1];
    float* out = (float*)d_out;

    norm_kernel<<<(BDIM * HW + NCLS * MDIM + 255) / 256, 256>>>(x1, x2);
    frag_kernel<<<(NA4 + NB4 + 255) / 256, 256>>>(x2);
    fused_metric_kernel<<<dim3(NQT * NSPL, NCLS, BDIM), 256>>>();
    finalize_kernel<<<BDIM * NCLS, 512>>>(out);
}